// round 6
// baseline (speedup 1.0000x reference)
#include <cuda_runtime.h>
#include <cstdint>

#define NB     16384
#define DTC    0.1f
#define FPB    128
#define THREADS 128

// ---------------- smem staging layout (words) ----------------
// staged[r][p][f] as float2: f-stride 2, pair-stride 264 (pad: bank-conflict-free
// flush), row-stride 4*264, double-buffered.
#define PS   264
#define RS   (4 * PS)            // 1056
#define SBUF (16 * RS)           // 16896
#define MEAS_OFF (2 * SBUF)      // 33792
#define MEAS_BUF 2048            // [m2][q2][f128][4]
#define CTRL_OFF (MEAS_OFF + 2 * MEAS_BUF)
#define CTRL_BUF 2048            // [q4][f128][4]
#define SMEM_WORDS (CTRL_OFF + 2 * CTRL_BUF)
#define SMEM_BYTES (SMEM_WORDS * 4)   // 167936

struct St  { float x0,x1,x2,x3,p00,p01,p02,p03,p11,p12,p13,p22,p23,p33; };
struct Cst { float q00,q01,q02,q03,q11,q12,q13,q22,q23,q33,r00,r01,r11; };

__device__ __forceinline__ void cp16(uint32_t dst, const float* src) {
    asm volatile("cp.async.ca.shared.global [%0], [%1], 16;\n" :: "r"(dst), "l"(src));
}

__device__ __forceinline__ void issue_full(
    uint32_t su, const float* __restrict__ meas, const float* __restrict__ ctrl,
    int b0, int tid, int buf, int s0)
{
#pragma unroll
    for (int j = 0; j < 4; j++) {                 // meas: 2m x 2q x 128f
        int id = tid + 128 * j;
        int f = id & 127, q = (id >> 7) & 1, m = id >> 8;
        cp16(su + (uint32_t)(MEAS_OFF + buf * MEAS_BUF + ((m * 2 + q) * 128 + f) * 4) * 4,
             meas + (size_t)(b0 + f) * 200 + m * 100 + s0 + 4 * q);
    }
#pragma unroll
    for (int j = 0; j < 4; j++) {                 // ctrl: 4q x 128f
        int id = tid + 128 * j;
        int f = id & 127, q = id >> 7;
        cp16(su + (uint32_t)(CTRL_OFF + buf * CTRL_BUF + (q * 128 + f) * 4) * 4,
             ctrl + (size_t)(b0 + f) * 200 + 2 * s0 + 4 * q);
    }
    asm volatile("cp.async.commit_group;\n" ::: "memory");
}

__device__ __forceinline__ void issue_tail(
    uint32_t su, const float* __restrict__ meas, const float* __restrict__ ctrl,
    int b0, int tid, int buf)
{
#pragma unroll
    for (int j = 0; j < 2; j++) {                 // meas q=0 only
        int id = tid + 128 * j;
        int f = id & 127, m = id >> 7;
        cp16(su + (uint32_t)(MEAS_OFF + buf * MEAS_BUF + ((m * 2) * 128 + f) * 4) * 4,
             meas + (size_t)(b0 + f) * 200 + m * 100 + 96);
    }
#pragma unroll
    for (int j = 0; j < 2; j++) {                 // ctrl q=0,1
        int id = tid + 128 * j;
        int f = id & 127, q = id >> 7;
        cp16(su + (uint32_t)(CTRL_OFF + buf * CTRL_BUF + (q * 128 + f) * 4) * 4,
             ctrl + (size_t)(b0 + f) * 200 + 192 + 4 * q);
    }
    asm volatile("cp.async.commit_group;\n" ::: "memory");
}

// one exact-collapsed UKF step; Pn via K*A_c^T (== K S K^T since K = A_c S^-1)
__device__ __forceinline__ void ukf_step(
    St& s, const Cst& c, float z0, float z1, float ux, float uy, float* o)
{
    const float xp0 = s.x0 + DTC * s.x2 + 0.5f * DTC * DTC * ux;
    const float xp1 = s.x1 + DTC * s.x3 + 0.5f * DTC * DTC * uy;
    const float xp2 = s.x2 + DTC * ux;
    const float xp3 = s.x3 + DTC * uy;

    const float a02 = s.p02 + DTC * s.p22;
    const float a03 = s.p03 + DTC * s.p23;
    const float a12 = s.p12 + DTC * s.p23;
    const float a13 = s.p13 + DTC * s.p33;
    const float a00 = s.p00 + DTC * s.p02 + DTC * a02;
    const float a11 = s.p11 + DTC * s.p13 + DTC * a13;
    const float a01 = s.p01 + DTC * s.p03 + DTC * a12;

    const float s00 = a00 + c.r00;
    const float s01 = a01 + c.r01;
    const float s11 = a11 + c.r11;
    const float idet = __fdividef(1.0f, s00 * s11 - s01 * s01);
    const float i00 =  s11 * idet;
    const float i01 = -s01 * idet;
    const float i11 =  s00 * idet;

    const float K00 = a00 * i00 + a01 * i01, K01 = a00 * i01 + a01 * i11;
    const float K10 = a01 * i00 + a11 * i01, K11 = a01 * i01 + a11 * i11;
    const float K20 = a02 * i00 + a12 * i01, K21 = a02 * i01 + a12 * i11;
    const float K30 = a03 * i00 + a13 * i01, K31 = a03 * i01 + a13 * i11;

    const float in0 = z0 - xp0, in1 = z1 - xp1;
    const float xn0 = xp0 + K00 * in0 + K01 * in1;
    const float xn1 = xp1 + K10 * in0 + K11 * in1;
    const float xn2 = xp2 + K20 * in0 + K21 * in1;
    const float xn3 = xp3 + K30 * in0 + K31 * in1;

    // P_new = A + Q - K * A_c^T   (columns A0={a00,a01,a02,a03}, A1={a01,a11,a12,a13})
    s.p00 = (a00 + c.q00) - (K00 * a00 + K01 * a01);
    s.p01 = (a01 + c.q01) - (K00 * a01 + K01 * a11);
    s.p02 = (a02 + c.q02) - (K00 * a02 + K01 * a12);
    s.p03 = (a03 + c.q03) - (K00 * a03 + K01 * a13);
    s.p11 = (a11 + c.q11) - (K10 * a01 + K11 * a11);
    s.p12 = (a12 + c.q12) - (K10 * a02 + K11 * a12);
    s.p13 = (a13 + c.q13) - (K10 * a03 + K11 * a13);
    s.p22 = (s.p22 + c.q22) - (K20 * a02 + K21 * a12);
    s.p23 = (s.p23 + c.q23) - (K20 * a03 + K21 * a13);
    s.p33 = (s.p33 + c.q33) - (K30 * a03 + K31 * a13);
    s.x0 = xn0; s.x1 = xn1; s.x2 = xn2; s.x3 = xn3;

    o[0] = xp0;  o[1] = xp1;
    o[2] = xn0;  o[3] = xn1;  o[4] = xn2;  o[5] = xn3;
    o[6]  = s.p00; o[7]  = s.p01; o[8]  = s.p02; o[9]  = s.p03;
    o[10] = s.p11; o[11] = s.p12; o[12] = s.p13;
    o[13] = s.p22; o[14] = s.p23; o[15] = s.p33;
}

// NS = 8 (full) or 4 (tail) steps; stages into `stage` (one SBUF region)
template <int NS>
__device__ __forceinline__ void compute_chunk(
    St& s, const Cst& c, float* sm, float* stage, int ibuf, int tid)
{
    const float* mb = sm + MEAS_OFF + ibuf * MEAS_BUF;
    const float* cb = sm + CTRL_OFF + ibuf * CTRL_BUF;

    float4 z0q[2], z1q[2], cq[4];
    z0q[0] = *reinterpret_cast<const float4*>(mb + (0 * 128 + tid) * 4);
    z1q[0] = *reinterpret_cast<const float4*>(mb + (2 * 128 + tid) * 4);
    cq[0]  = *reinterpret_cast<const float4*>(cb + (0 * 128 + tid) * 4);
    cq[1]  = *reinterpret_cast<const float4*>(cb + (1 * 128 + tid) * 4);
    if (NS == 8) {
        z0q[1] = *reinterpret_cast<const float4*>(mb + (1 * 128 + tid) * 4);
        z1q[1] = *reinterpret_cast<const float4*>(mb + (3 * 128 + tid) * 4);
        cq[2]  = *reinterpret_cast<const float4*>(cb + (2 * 128 + tid) * 4);
        cq[3]  = *reinterpret_cast<const float4*>(cb + (3 * 128 + tid) * 4);
    } else {
        z0q[1] = z0q[0]; z1q[1] = z1q[0]; cq[2] = cq[0]; cq[3] = cq[1];
    }
    const float z0s[8] = {z0q[0].x,z0q[0].y,z0q[0].z,z0q[0].w,
                          z0q[1].x,z0q[1].y,z0q[1].z,z0q[1].w};
    const float z1s[8] = {z1q[0].x,z1q[0].y,z1q[0].z,z1q[0].w,
                          z1q[1].x,z1q[1].y,z1q[1].z,z1q[1].w};
    const float uxs[8] = {cq[0].x,cq[0].z,cq[1].x,cq[1].z,
                          cq[2].x,cq[2].z,cq[3].x,cq[3].z};
    const float uys[8] = {cq[0].y,cq[0].w,cq[1].y,cq[1].w,
                          cq[2].y,cq[2].w,cq[3].y,cq[3].w};

    float prev[16];
#pragma unroll
    for (int sp = 0; sp < NS; sp++) {
        float cur[16];
        ukf_step(s, c, z0s[sp], z1s[sp], uxs[sp], uys[sp], cur);
        if (sp & 1) {
            float* sb = stage + (sp >> 1) * PS + tid * 2;
#pragma unroll
            for (int r = 0; r < 16; r++)
                *reinterpret_cast<float2*>(sb + r * RS) = make_float2(prev[r], cur[r]);
        } else {
#pragma unroll
            for (int r = 0; r < 16; r++) prev[r] = cur[r];
        }
    }
}

__device__ __forceinline__ int row_map(int R) {
    constexpr int MAP[22] = {0,1,2,3,4,5,
                             6,7,8,9, 7,10,11,12, 8,11,13,14, 9,12,14,15};
    return MAP[R];
}

// flush one 8-step chunk from `stage`
__device__ __forceinline__ void flush_full(
    const float* __restrict__ stage, float* __restrict__ preds,
    float* __restrict__ states, float* __restrict__ covs,
    int blk, int tid, int s0)
{
    const int h  = tid & 1;
    const int f0 = tid >> 1;
#pragma unroll
    for (int it = 0; it < 2; it++) {
        const int f  = f0 + 64 * it;
        const int gb = blk * FPB + f;
        const float* base = stage + f * 2 + (2 * h) * PS;
        float* pp = preds  + (size_t)gb * 200  + s0 + 4 * h;
        float* ps = states + (size_t)gb * 400  + s0 + 4 * h;
        float* pc = covs   + (size_t)gb * 1600 + s0 + 4 * h;
#pragma unroll
        for (int R = 0; R < 22; R++) {
            const int r = row_map(R);
            float2 lo = *reinterpret_cast<const float2*>(base + r * RS);
            float2 hi = *reinterpret_cast<const float2*>(base + r * RS + PS);
            float4 v = make_float4(lo.x, lo.y, hi.x, hi.y);
            float* dst = (R < 2) ? (pp + R * 100)
                       : (R < 6) ? (ps + (R - 2) * 100)
                                 : (pc + (R - 6) * 100);
            *reinterpret_cast<float4*>(dst) = v;
        }
    }
}

__global__ __launch_bounds__(THREADS, 1) void ukf_kernel(
    const float* __restrict__ meas, const float* __restrict__ state0,
    const float* __restrict__ cov0, const float* __restrict__ ctrl,
    const float* __restrict__ Qm,   const float* __restrict__ Rm,
    float* __restrict__ preds, float* __restrict__ states, float* __restrict__ covs)
{
    extern __shared__ float sm[];
    const uint32_t su = (uint32_t)__cvta_generic_to_shared(sm);
    const int tid = threadIdx.x;
    const int blk = blockIdx.x;
    const int b0  = blk * FPB;
    const int b   = b0 + tid;

    St s;
    {
        float4 xv = *reinterpret_cast<const float4*>(state0 + (size_t)b * 4);
        s.x0 = xv.x; s.x1 = xv.y; s.x2 = xv.z; s.x3 = xv.w;
        const float4* pv = reinterpret_cast<const float4*>(cov0 + (size_t)b * 16);
        float4 r0 = pv[0], r1 = pv[1], r2 = pv[2], r3 = pv[3];
        s.p00 = r0.x; s.p01 = r0.y; s.p02 = r0.z; s.p03 = r0.w;
        s.p11 = r1.y; s.p12 = r1.z; s.p13 = r1.w;
        s.p22 = r2.z; s.p23 = r2.w; s.p33 = r3.w;
    }
    Cst c;
    c.q00 = Qm[0];  c.q01 = Qm[1];  c.q02 = Qm[2];  c.q03 = Qm[3];
    c.q11 = Qm[5];  c.q12 = Qm[6];  c.q13 = Qm[7];
    c.q22 = Qm[10]; c.q23 = Qm[11]; c.q33 = Qm[15];
    c.r00 = Rm[0];  c.r01 = Rm[1];  c.r11 = Rm[3];

    float* stg[2] = { sm, sm + SBUF };

    issue_full(su, meas, ctrl, b0, tid, 0, 0);

    // ---- ch = 0 ----
    issue_full(su, meas, ctrl, b0, tid, 1, 8);
    asm volatile("cp.async.wait_group 1;\n" ::: "memory");
    __syncthreads();
    compute_chunk<8>(s, c, sm, stg[0], 0, tid);

    // ---- ch = 1..11 : flush(ch-1) + compute(ch) fused, one barrier per chunk ----
#pragma unroll 1
    for (int ch = 1; ch < 12; ch++) {
        if (ch < 11) issue_full(su, meas, ctrl, b0, tid, (ch + 1) & 1, (ch + 1) * 8);
        else         issue_tail(su, meas, ctrl, b0, tid, 0);
        asm volatile("cp.async.wait_group 1;\n" ::: "memory");
        __syncthreads();
        flush_full(stg[(ch - 1) & 1], preds, states, covs, blk, tid, (ch - 1) * 8);
        compute_chunk<8>(s, c, sm, stg[ch & 1], ch & 1, tid);
    }

    // ---- ch = 12 (tail, 4 steps) ----
    asm volatile("cp.async.wait_group 0;\n" ::: "memory");
    __syncthreads();
    flush_full(stg[1], preds, states, covs, blk, tid, 88);
    compute_chunk<4>(s, c, sm, stg[0], 0, tid);
    __syncthreads();

    // tail flush: 4 steps at s0 = 96 (pairs 0,1 of stg[0])
    {
        const int f  = tid;
        const int gb = blk * FPB + f;
        const float* base = stg[0] + f * 2;
        float* pp = preds  + (size_t)gb * 200  + 96;
        float* ps = states + (size_t)gb * 400  + 96;
        float* pc = covs   + (size_t)gb * 1600 + 96;
#pragma unroll
        for (int R = 0; R < 22; R++) {
            const int r = row_map(R);
            float2 lo = *reinterpret_cast<const float2*>(base + r * RS);
            float2 hi = *reinterpret_cast<const float2*>(base + r * RS + PS);
            float4 v = make_float4(lo.x, lo.y, hi.x, hi.y);
            float* dst = (R < 2) ? (pp + R * 100)
                       : (R < 6) ? (ps + (R - 2) * 100)
                                 : (pc + (R - 6) * 100);
            *reinterpret_cast<float4*>(dst) = v;
        }
    }
}

extern "C" void kernel_launch(void* const* d_in, const int* in_sizes, int n_in,
                              void* d_out, int out_size)
{
    const float* meas  = (const float*)d_in[0];
    const float* state = (const float*)d_in[1];
    const float* cov   = (const float*)d_in[2];
    const float* ctrl  = (const float*)d_in[3];
    const float* Q     = (const float*)d_in[4];
    const float* R     = (const float*)d_in[5];

    float* out    = (float*)d_out;
    float* preds  = out;                         // 16384*2*100
    float* states = preds  + (size_t)NB * 200;   // 16384*4*100
    float* covs   = states + (size_t)NB * 400;   // 16384*16*100

    static int smem_set = 0;
    if (!smem_set) {
        cudaFuncSetAttribute(ukf_kernel,
                             cudaFuncAttributeMaxDynamicSharedMemorySize, SMEM_BYTES);
        smem_set = 1;
    }

    ukf_kernel<<<NB / FPB, THREADS, SMEM_BYTES>>>(meas, state, cov, ctrl, Q, R,
                                                  preds, states, covs);
}